// round 1
// baseline (speedup 1.0000x reference)
#include <cuda_runtime.h>
#include <math.h>

#define V 32000
#define H 1024
#define T 32
#define B 64
#define SOS_INDEX 1
#define EOS_INDEX 2
#define GATES (4*H)

// Persistent decode state (no allocations allowed)
__device__ float g_x[B*H];       // current input embedding
__device__ float g_h[B*H];       // hidden state
__device__ float g_c[B*H];       // cell state
__device__ float g_gates[B*GATES];

// ---------------------------------------------------------------------------
// Init: x0 = E[SOS], h = encoder_hidden, c = encoder_cell
// ---------------------------------------------------------------------------
__global__ void init_kernel(const float* __restrict__ E,
                            const float* __restrict__ eh,
                            const float* __restrict__ ec) {
    int i = blockIdx.x * blockDim.x + threadIdx.x;   // 0 .. B*H
    int k = i & (H - 1);
    g_x[i] = E[SOS_INDEX * H + k];
    g_h[i] = eh[i];
    g_c[i] = ec[i];
}

// ---------------------------------------------------------------------------
// GEMM tiles: BM=64 (full batch), BN=64, BK=32, 256 threads, 4x4 microtile
// ---------------------------------------------------------------------------
#define BM 64
#define BN 64
#define BK 32
#define APAD 4   // row length 68 floats = 272B, 16B aligned

// gates[b][j] = sum_k x[b][k]*Wih[j][k] + sum_k h[b][k]*Whh[j][k] + bih[j]+bhh[j]
__global__ __launch_bounds__(256)
void gates_gemm(const float* __restrict__ Wih, const float* __restrict__ Whh,
                const float* __restrict__ bih, const float* __restrict__ bhh) {
    __shared__ __align__(16) float As[BK][BM + APAD];
    __shared__ __align__(16) float Bs[BK][BN + APAD];

    const int n0  = blockIdx.x * BN;
    const int tid = threadIdx.x;
    const int tm  = tid >> 4;        // 0..15
    const int tn  = tid & 15;        // 0..15
    const int lm  = tid >> 3;        // 0..31 loader row
    const int lk4 = (tid & 7) * 4;   // loader k offset (float4)

    float acc[4][4];
    #pragma unroll
    for (int i = 0; i < 4; i++)
        #pragma unroll
        for (int j = 0; j < 4; j++) acc[i][j] = 0.f;

    for (int k0 = 0; k0 < 2 * H; k0 += BK) {
        const int kk = k0 + lk4;
        // A tile: virtual A = concat(x, h) along k
        #pragma unroll
        for (int r = 0; r < 2; r++) {
            int m = lm + r * 32;
            const float* src = (kk < H) ? (g_x + m * H + kk)
                                        : (g_h + m * H + (kk - H));
            float4 v = *reinterpret_cast<const float4*>(src);
            As[lk4 + 0][m] = v.x; As[lk4 + 1][m] = v.y;
            As[lk4 + 2][m] = v.z; As[lk4 + 3][m] = v.w;
        }
        // B tile: virtual W = concat(Wih, Whh) along k (both [4096][1024] row-major)
        #pragma unroll
        for (int r = 0; r < 2; r++) {
            int n = lm + r * 32;
            const float* src = (kk < H) ? (Wih + (size_t)(n0 + n) * H + kk)
                                        : (Whh + (size_t)(n0 + n) * H + (kk - H));
            float4 v = *reinterpret_cast<const float4*>(src);
            Bs[lk4 + 0][n] = v.x; Bs[lk4 + 1][n] = v.y;
            Bs[lk4 + 2][n] = v.z; Bs[lk4 + 3][n] = v.w;
        }
        __syncthreads();

        #pragma unroll
        for (int k = 0; k < BK; k++) {
            float4 a  = *reinterpret_cast<const float4*>(&As[k][tm * 4]);
            float4 bv = *reinterpret_cast<const float4*>(&Bs[k][tn * 4]);
            acc[0][0] += a.x * bv.x; acc[0][1] += a.x * bv.y;
            acc[0][2] += a.x * bv.z; acc[0][3] += a.x * bv.w;
            acc[1][0] += a.y * bv.x; acc[1][1] += a.y * bv.y;
            acc[1][2] += a.y * bv.z; acc[1][3] += a.y * bv.w;
            acc[2][0] += a.z * bv.x; acc[2][1] += a.z * bv.y;
            acc[2][2] += a.z * bv.z; acc[2][3] += a.z * bv.w;
            acc[3][0] += a.w * bv.x; acc[3][1] += a.w * bv.y;
            acc[3][2] += a.w * bv.z; acc[3][3] += a.w * bv.w;
        }
        __syncthreads();
    }

    #pragma unroll
    for (int i = 0; i < 4; i++) {
        int m = tm * 4 + i;
        #pragma unroll
        for (int j = 0; j < 4; j++) {
            int n = n0 + tn * 4 + j;
            g_gates[m * GATES + n] = acc[i][j] + bih[n] + bhh[n];
        }
    }
}

// logits[b][v] = sum_k h[b][k]*Wout[v][k] + bout[v]   -> written into d_out slice
__global__ __launch_bounds__(256)
void logits_gemm(const float* __restrict__ Wout, const float* __restrict__ bout,
                 float* __restrict__ out) {
    __shared__ __align__(16) float As[BK][BM + APAD];
    __shared__ __align__(16) float Bs[BK][BN + APAD];

    const int n0  = blockIdx.x * BN;
    const int tid = threadIdx.x;
    const int tm  = tid >> 4;
    const int tn  = tid & 15;
    const int lm  = tid >> 3;
    const int lk4 = (tid & 7) * 4;

    float acc[4][4];
    #pragma unroll
    for (int i = 0; i < 4; i++)
        #pragma unroll
        for (int j = 0; j < 4; j++) acc[i][j] = 0.f;

    for (int k0 = 0; k0 < H; k0 += BK) {
        const int kk = k0 + lk4;
        #pragma unroll
        for (int r = 0; r < 2; r++) {
            int m = lm + r * 32;
            float4 v = *reinterpret_cast<const float4*>(g_h + m * H + kk);
            As[lk4 + 0][m] = v.x; As[lk4 + 1][m] = v.y;
            As[lk4 + 2][m] = v.z; As[lk4 + 3][m] = v.w;
        }
        #pragma unroll
        for (int r = 0; r < 2; r++) {
            int n = lm + r * 32;
            float4 v = *reinterpret_cast<const float4*>(Wout + (size_t)(n0 + n) * H + kk);
            Bs[lk4 + 0][n] = v.x; Bs[lk4 + 1][n] = v.y;
            Bs[lk4 + 2][n] = v.z; Bs[lk4 + 3][n] = v.w;
        }
        __syncthreads();

        #pragma unroll
        for (int k = 0; k < BK; k++) {
            float4 a  = *reinterpret_cast<const float4*>(&As[k][tm * 4]);
            float4 bv = *reinterpret_cast<const float4*>(&Bs[k][tn * 4]);
            acc[0][0] += a.x * bv.x; acc[0][1] += a.x * bv.y;
            acc[0][2] += a.x * bv.z; acc[0][3] += a.x * bv.w;
            acc[1][0] += a.y * bv.x; acc[1][1] += a.y * bv.y;
            acc[1][2] += a.y * bv.z; acc[1][3] += a.y * bv.w;
            acc[2][0] += a.z * bv.x; acc[2][1] += a.z * bv.y;
            acc[2][2] += a.z * bv.z; acc[2][3] += a.z * bv.w;
            acc[3][0] += a.w * bv.x; acc[3][1] += a.w * bv.y;
            acc[3][2] += a.w * bv.z; acc[3][3] += a.w * bv.w;
        }
        __syncthreads();
    }

    #pragma unroll
    for (int i = 0; i < 4; i++) {
        int m = tm * 4 + i;
        #pragma unroll
        for (int j = 0; j < 4; j++) {
            int n = n0 + tn * 4 + j;
            out[(size_t)m * V + n] = acc[i][j] + bout[n];
        }
    }
}

// ---------------------------------------------------------------------------
// LSTM cell elementwise (PyTorch gate order i,f,g,o)
// ---------------------------------------------------------------------------
__global__ void cell_kernel() {
    int i = blockIdx.x * blockDim.x + threadIdx.x;   // B*H
    int b = i >> 10;
    int j = i & (H - 1);
    const float* g = g_gates + b * GATES;
    float ig = g[j], fg = g[j + H], gg = g[j + 2 * H], og = g[j + 3 * H];
    float c  = g_c[i];
    float si = 1.f / (1.f + expf(-ig));
    float sf = 1.f / (1.f + expf(-fg));
    float so = 1.f / (1.f + expf(-og));
    float cn = sf * c + si * tanhf(gg);
    float hn = so * tanhf(cn);
    g_c[i] = cn;
    g_h[i] = hn;
}

// ---------------------------------------------------------------------------
// Per-batch-row: argmax (first-index tiebreak, matching jnp.argmax), softmax
// EOS prob, and greedy feedback gather x_next = E[argmax]
// ---------------------------------------------------------------------------
__global__ __launch_bounds__(256)
void softmax_argmax(const float* __restrict__ logits, const float* __restrict__ E,
                    float* __restrict__ mask_out) {
    const int b   = blockIdx.x;
    const int tid = threadIdx.x;
    const float* row = logits + (size_t)b * V;

    float best = -INFINITY; int besti = 0x7fffffff;
    for (int v = tid; v < V; v += 256) {
        float x = row[v];
        if (x > best) { best = x; besti = v; }   // scan order keeps lowest index
    }
    __shared__ float smax[256];
    __shared__ int   sidx[256];
    smax[tid] = best; sidx[tid] = besti;
    __syncthreads();
    for (int s = 128; s > 0; s >>= 1) {
        if (tid < s) {
            float o = smax[tid + s]; int oi = sidx[tid + s];
            if (o > smax[tid] || (o == smax[tid] && oi < sidx[tid])) {
                smax[tid] = o; sidx[tid] = oi;
            }
        }
        __syncthreads();
    }
    const float gmax = smax[0];
    const int   amax = sidx[0];

    float sum = 0.f;
    for (int v = tid; v < V; v += 256) sum += expf(row[v] - gmax);
    __shared__ float ssum[256];
    ssum[tid] = sum;
    __syncthreads();
    for (int s = 128; s > 0; s >>= 1) {
        if (tid < s) ssum[tid] += ssum[tid + s];
        __syncthreads();
    }
    if (tid == 0) mask_out[b] = expf(row[EOS_INDEX] - gmax) / ssum[0];

    // greedy feedback: x_next = E[argmax]
    for (int k = tid; k < H; k += 256)
        g_x[b * H + k] = E[(size_t)amax * H + k];
}

// ---------------------------------------------------------------------------
extern "C" void kernel_launch(void* const* d_in, const int* in_sizes, int n_in,
                              void* d_out, int out_size) {
    const float* E    = (const float*)d_in[0];
    const float* Wih  = (const float*)d_in[1];
    const float* Whh  = (const float*)d_in[2];
    const float* bih  = (const float*)d_in[3];
    const float* bhh  = (const float*)d_in[4];
    const float* Wout = (const float*)d_in[5];
    const float* bout = (const float*)d_in[6];
    const float* eh   = (const float*)d_in[7];
    const float* ec   = (const float*)d_in[8];
    // d_in[9] target_var (unused in eval-mode greedy decode), d_in[10] scalar len

    float* out   = (float*)d_out;                       // [T][B][V] logits
    float* masks = out + (size_t)T * B * V;             // [T][B]

    init_kernel<<<(B * H) / 256, 256>>>(E, eh, ec);
    for (int t = 0; t < T; t++) {
        float* lg = out + (size_t)t * B * V;
        gates_gemm<<<GATES / BN, 256>>>(Wih, Whh, bih, bhh);
        cell_kernel<<<(B * H) / 256, 256>>>();
        logits_gemm<<<V / BN, 256>>>(Wout, bout, lg);
        softmax_argmax<<<B, 256>>>(lg, E, masks + t * B);
    }
}

// round 3
// speedup vs baseline: 1.3672x; 1.3672x over previous
#include <cuda_runtime.h>
#include <math.h>
#include <stdint.h>

#define V 32000
#define H 1024
#define T 32
#define B 64
#define SOS_INDEX 1
#define EOS_INDEX 2
#define GATES (4*H)

// Persistent decode state (no allocations allowed)
__device__ float g_x[B*H];       // current input embedding
__device__ float g_h[B*H];       // hidden state
__device__ float g_c[B*H];       // cell state
__device__ float g_gates[B*GATES];

// ---------------------------------------------------------------------------
// Init: x0 = E[SOS], h = encoder_hidden, c = encoder_cell
// ---------------------------------------------------------------------------
__global__ void init_kernel(const float* __restrict__ E,
                            const float* __restrict__ eh,
                            const float* __restrict__ ec) {
    int i = blockIdx.x * blockDim.x + threadIdx.x;   // 0 .. B*H
    int k = i & (H - 1);
    g_x[i] = E[SOS_INDEX * H + k];
    g_h[i] = eh[i];
    g_c[i] = ec[i];
}

// ---------------------------------------------------------------------------
// TF32 helpers (3xTF32 fp32 emulation)
// ---------------------------------------------------------------------------
__device__ __forceinline__ uint32_t f2tf32(float x) {
    uint32_t r;
    asm("cvt.rna.tf32.f32 %0, %1;" : "=r"(r) : "f"(x));
    return r;
}
__device__ __forceinline__ void split_tf32(float x, uint32_t& hi, uint32_t& lo) {
    hi = f2tf32(x);
    float r = x - __uint_as_float(hi);
    lo = f2tf32(r);
}
__device__ __forceinline__ void mma_tf32(float c[4],
                                         uint32_t a0, uint32_t a1, uint32_t a2, uint32_t a3,
                                         uint32_t b0, uint32_t b1) {
    asm volatile(
        "mma.sync.aligned.m16n8k8.row.col.f32.tf32.tf32.f32 "
        "{%0,%1,%2,%3}, {%4,%5,%6,%7}, {%8,%9}, {%0,%1,%2,%3};"
        : "+f"(c[0]), "+f"(c[1]), "+f"(c[2]), "+f"(c[3])
        : "r"(a0), "r"(a1), "r"(a2), "r"(a3), "r"(b0), "r"(b1));
}

// ---------------------------------------------------------------------------
// Tensor-core GEMM: C[64 x N] = A[64 x KTOT] * W[N x KTOT]^T + bias
//   CONCAT=false: A = g_h, W = Wa (KTOT=H), bias = bias1
//   CONCAT=true : A = [g_x | g_h], W = [Wa | Wb] along k, bias = bias1+bias2
// BM=64 rows (full batch), BN columns per block, BK=32 per tile.
// 256 threads = 8 warps laid out 4(M) x 2(N); warp tile = 16 x (BN/2).
// ---------------------------------------------------------------------------
#define BK 32
#define SKEW 4

template<int KTOT, int BN, bool CONCAT>
__global__ __launch_bounds__(256)
void mma_gemm(const float* __restrict__ Wa, const float* __restrict__ Wb,
              const float* __restrict__ bias1, const float* __restrict__ bias2,
              float* __restrict__ out, int ldc) {
    constexpr int NF = BN / 16;           // n-fragments (8 wide) per warp
    __shared__ __align__(16) float As[64][BK + SKEW];
    __shared__ __align__(16) float Bs[BN][BK + SKEW];

    const int n0blk = blockIdx.x * BN;
    const int tid   = threadIdx.x;
    const int warp  = tid >> 5;
    const int lane  = tid & 31;
    const int gid   = lane >> 2;          // group id 0..7
    const int tig   = lane & 3;           // thread in group 0..3

    const int m0  = (warp >> 1) * 16;     // warp M offset (0,16,32,48)
    const int n0w = (warp & 1) * (BN / 2);// warp N offset

    const int lm  = tid >> 3;             // loader row 0..31
    const int lk4 = (tid & 7) * 4;        // loader k offset (float4)

    float c[NF][4];
    #pragma unroll
    for (int nf = 0; nf < NF; nf++)
        #pragma unroll
        for (int j = 0; j < 4; j++) c[nf][j] = 0.f;

    for (int k0 = 0; k0 < KTOT; k0 += BK) {
        const int kg = k0 + lk4;
        // ---- A tile (64 x 32) ----
        #pragma unroll
        for (int r = 0; r < 64; r += 32) {
            int m = lm + r;
            const float* src;
            if (CONCAT)
                src = (kg < H) ? (g_x + m * H + kg) : (g_h + m * H + (kg - H));
            else
                src = g_h + m * H + kg;
            float4 v = *reinterpret_cast<const float4*>(src);
            As[m][lk4 + 0] = v.x; As[m][lk4 + 1] = v.y;
            As[m][lk4 + 2] = v.z; As[m][lk4 + 3] = v.w;
        }
        // ---- B tile (BN x 32) ----
        #pragma unroll
        for (int r = 0; r < BN; r += 32) {
            int n = lm + r;
            const float* src;
            if (CONCAT)
                src = (kg < H) ? (Wa + (size_t)(n0blk + n) * H + kg)
                               : (Wb + (size_t)(n0blk + n) * H + (kg - H));
            else
                src = Wa + (size_t)(n0blk + n) * KTOT + kg;
            float4 v = *reinterpret_cast<const float4*>(src);
            Bs[n][lk4 + 0] = v.x; Bs[n][lk4 + 1] = v.y;
            Bs[n][lk4 + 2] = v.z; Bs[n][lk4 + 3] = v.w;
        }
        __syncthreads();

        #pragma unroll
        for (int ks = 0; ks < BK / 8; ks++) {
            const int kk = ks * 8;
            // A fragment (m16 x k8), split into hi/lo tf32
            float a0f = As[m0 + gid    ][kk + tig];
            float a1f = As[m0 + gid + 8][kk + tig];
            float a2f = As[m0 + gid    ][kk + tig + 4];
            float a3f = As[m0 + gid + 8][kk + tig + 4];
            uint32_t ah0, al0, ah1, al1, ah2, al2, ah3, al3;
            split_tf32(a0f, ah0, al0);
            split_tf32(a1f, ah1, al1);
            split_tf32(a2f, ah2, al2);
            split_tf32(a3f, ah3, al3);

            #pragma unroll
            for (int nf = 0; nf < NF; nf++) {
                int n = n0w + nf * 8 + gid;
                float b0f = Bs[n][kk + tig];
                float b1f = Bs[n][kk + tig + 4];
                uint32_t bh0, bl0, bh1, bl1;
                split_tf32(b0f, bh0, bl0);
                split_tf32(b1f, bh1, bl1);
                // C += Al*Bh + Ah*Bl + Ah*Bh  (3xTF32 ~ fp32)
                mma_tf32(c[nf], al0, al1, al2, al3, bh0, bh1);
                mma_tf32(c[nf], ah0, ah1, ah2, ah3, bl0, bl1);
                mma_tf32(c[nf], ah0, ah1, ah2, ah3, bh0, bh1);
            }
        }
        __syncthreads();
    }

    // ---- epilogue: bias + store (float2 per row-fragment) ----
    const int mr0 = m0 + gid;
    const int mr1 = m0 + gid + 8;
    #pragma unroll
    for (int nf = 0; nf < NF; nf++) {
        int nn = n0blk + n0w + nf * 8 + tig * 2;
        float b0 = bias1[nn]     + (CONCAT ? bias2[nn]     : 0.f);
        float b1 = bias1[nn + 1] + (CONCAT ? bias2[nn + 1] : 0.f);
        float2 v0 = make_float2(c[nf][0] + b0, c[nf][1] + b1);
        float2 v1 = make_float2(c[nf][2] + b0, c[nf][3] + b1);
        *reinterpret_cast<float2*>(out + (size_t)mr0 * ldc + nn) = v0;
        *reinterpret_cast<float2*>(out + (size_t)mr1 * ldc + nn) = v1;
    }
}

// ---------------------------------------------------------------------------
// LSTM cell elementwise (PyTorch gate order i,f,g,o)
// ---------------------------------------------------------------------------
__global__ void cell_kernel() {
    int i = blockIdx.x * blockDim.x + threadIdx.x;   // B*H
    int b = i >> 10;
    int j = i & (H - 1);
    const float* g = g_gates + b * GATES;
    float ig = g[j], fg = g[j + H], gg = g[j + 2 * H], og = g[j + 3 * H];
    float c  = g_c[i];
    float si = 1.f / (1.f + expf(-ig));
    float sf = 1.f / (1.f + expf(-fg));
    float so = 1.f / (1.f + expf(-og));
    float cn = sf * c + si * tanhf(gg);
    float hn = so * tanhf(cn);
    g_c[i] = cn;
    g_h[i] = hn;
}

// ---------------------------------------------------------------------------
// Per-batch-row: argmax (first-index tiebreak), softmax EOS prob,
// greedy feedback gather x_next = E[argmax]
// ---------------------------------------------------------------------------
__global__ __launch_bounds__(256)
void softmax_argmax(const float* __restrict__ logits, const float* __restrict__ E,
                    float* __restrict__ mask_out) {
    const int b   = blockIdx.x;
    const int tid = threadIdx.x;
    const float* row = logits + (size_t)b * V;

    float best = -INFINITY; int besti = 0x7fffffff;
    for (int v = tid; v < V; v += 256) {
        float x = row[v];
        if (x > best) { best = x; besti = v; }   // scan order keeps lowest index
    }
    __shared__ float smax[256];
    __shared__ int   sidx[256];
    smax[tid] = best; sidx[tid] = besti;
    __syncthreads();
    for (int s = 128; s > 0; s >>= 1) {
        if (tid < s) {
            float o = smax[tid + s]; int oi = sidx[tid + s];
            if (o > smax[tid] || (o == smax[tid] && oi < sidx[tid])) {
                smax[tid] = o; sidx[tid] = oi;
            }
        }
        __syncthreads();
    }
    const float gmax = smax[0];
    const int   amax = sidx[0];

    float sum = 0.f;
    for (int v = tid; v < V; v += 256) sum += expf(row[v] - gmax);
    __shared__ float ssum[256];
    ssum[tid] = sum;
    __syncthreads();
    for (int s = 128; s > 0; s >>= 1) {
        if (tid < s) ssum[tid] += ssum[tid + s];
        __syncthreads();
    }
    if (tid == 0) mask_out[b] = expf(row[EOS_INDEX] - gmax) / ssum[0];

    // greedy feedback: x_next = E[argmax]
    for (int k = tid; k < H; k += 256)
        g_x[b * H + k] = E[(size_t)amax * H + k];
}

// ---------------------------------------------------------------------------
extern "C" void kernel_launch(void* const* d_in, const int* in_sizes, int n_in,
                              void* d_out, int out_size) {
    const float* E    = (const float*)d_in[0];
    const float* Wih  = (const float*)d_in[1];
    const float* Whh  = (const float*)d_in[2];
    const float* bih  = (const float*)d_in[3];
    const float* bhh  = (const float*)d_in[4];
    const float* Wout = (const float*)d_in[5];
    const float* bout = (const float*)d_in[6];
    const float* eh   = (const float*)d_in[7];
    const float* ec   = (const float*)d_in[8];

    float* out   = (float*)d_out;                       // [T][B][V] logits
    float* masks = out + (size_t)T * B * V;             // [T][B]

    // CRITICAL: resolve the DEVICE address of g_gates. Referencing a
    // __device__ symbol directly in host code yields the host shadow
    // address (silently "works" on GB300 via ATS, writing host memory).
    void* gates_dev = nullptr;
    cudaGetSymbolAddress(&gates_dev, g_gates);
    float* gates_ptr = (float*)gates_dev;

    init_kernel<<<(B * H) / 256, 256>>>(E, eh, ec);
    for (int t = 0; t < T; t++) {
        float* lg = out + (size_t)t * B * V;
        // gates: [64 x 4096] = [x|h] * [Wih|Whh]^T, BN=32 -> 128 blocks
        mma_gemm<2 * H, 32, true><<<GATES / 32, 256>>>(
            Wih, Whh, bih, bhh, gates_ptr, GATES);
        cell_kernel<<<(B * H) / 256, 256>>>();
        // logits: [64 x 32000] = h * Wout^T, BN=64 -> 500 blocks
        mma_gemm<H, 64, false><<<V / 64, 256>>>(
            Wout, nullptr, bout, nullptr, lg, V);
        softmax_argmax<<<B, 256>>>(lg, E, masks + t * B);
    }
}

// round 4
// speedup vs baseline: 1.6338x; 1.1950x over previous
#include <cuda_runtime.h>
#include <math.h>
#include <stdint.h>

#define V 32000
#define H 1024
#define T 32
#define B 64
#define SOS_INDEX 1
#define EOS_INDEX 2
#define GATES (4*H)

// Persistent decode state (no allocations allowed)
__device__ float g_x[B*H];       // current input embedding
__device__ float g_h[B*H];       // hidden state
__device__ float g_c[B*H];       // cell state
__device__ float g_gates[B*GATES];

// ---------------------------------------------------------------------------
__global__ void init_kernel(const float* __restrict__ E,
                            const float* __restrict__ eh,
                            const float* __restrict__ ec) {
    int i = blockIdx.x * blockDim.x + threadIdx.x;   // 0 .. B*H
    int k = i & (H - 1);
    g_x[i] = E[SOS_INDEX * H + k];
    g_h[i] = eh[i];
    g_c[i] = ec[i];
}

// ---------------------------------------------------------------------------
// TF32 helpers (3xTF32 fp32 emulation)
// ---------------------------------------------------------------------------
__device__ __forceinline__ uint32_t f2tf32(float x) {
    uint32_t r;
    asm("cvt.rna.tf32.f32 %0, %1;" : "=r"(r) : "f"(x));
    return r;
}
__device__ __forceinline__ void split_tf32(float x, float& hi, float& lo) {
    uint32_t h = f2tf32(x);
    hi = __uint_as_float(h);
    lo = __uint_as_float(f2tf32(x - hi));
}
__device__ __forceinline__ void mma_tf32(float c[4],
                                         uint32_t a0, uint32_t a1, uint32_t a2, uint32_t a3,
                                         uint32_t b0, uint32_t b1) {
    asm volatile(
        "mma.sync.aligned.m16n8k8.row.col.f32.tf32.tf32.f32 "
        "{%0,%1,%2,%3}, {%4,%5,%6,%7}, {%8,%9}, {%0,%1,%2,%3};"
        : "+f"(c[0]), "+f"(c[1]), "+f"(c[2]), "+f"(c[3])
        : "r"(a0), "r"(a1), "r"(a2), "r"(a3), "r"(b0), "r"(b1));
}

// ---------------------------------------------------------------------------
// Tensor-core GEMM: C[64 x N] = A[64 x KTOT] * W[N x KTOT]^T + bias
// hi/lo tf32 split is done ONCE at the load stage into SMEM; the inner loop
// is pure LDS + HMMA. Register double-buffering hides GMEM latency.
// ---------------------------------------------------------------------------
#define BK 32
#define SKEW 4

template<int KTOT, int BN, bool CONCAT>
__global__ __launch_bounds__(256)
void mma_gemm(const float* __restrict__ Wa, const float* __restrict__ Wb,
              const float* __restrict__ bias1, const float* __restrict__ bias2,
              float* __restrict__ out, int ldc) {
    constexpr int NF = BN / 16;           // n-fragments (8 wide) per warp
    constexpr int BR = BN / 32;           // B loader row chunks
    __shared__ __align__(16) float AsH[64][BK + SKEW];
    __shared__ __align__(16) float AsL[64][BK + SKEW];
    __shared__ __align__(16) float BsH[BN][BK + SKEW];
    __shared__ __align__(16) float BsL[BN][BK + SKEW];

    const int n0blk = blockIdx.x * BN;
    const int tid   = threadIdx.x;
    const int warp  = tid >> 5;
    const int lane  = tid & 31;
    const int gid   = lane >> 2;          // group id 0..7
    const int tig   = lane & 3;           // thread in group 0..3

    const int m0  = (warp >> 1) * 16;     // warp M offset (0,16,32,48)
    const int n0w = (warp & 1) * (BN / 2);// warp N offset

    const int lm  = tid >> 3;             // loader row 0..31
    const int lk4 = (tid & 7) * 4;        // loader k offset (float4)

    float4 aR[2];
    float4 bR[BR];

    auto gload = [&](int k0) {
        const int kg = k0 + lk4;
        #pragma unroll
        for (int r = 0; r < 2; r++) {
            int m = lm + r * 32;
            const float* src = CONCAT
                ? ((kg < H) ? (g_x + m * H + kg) : (g_h + m * H + (kg - H)))
                : (g_h + m * H + kg);
            aR[r] = *reinterpret_cast<const float4*>(src);
        }
        #pragma unroll
        for (int r = 0; r < BR; r++) {
            int n = lm + r * 32;
            const float* src = CONCAT
                ? ((kg < H) ? (Wa + (size_t)(n0blk + n) * H + kg)
                            : (Wb + (size_t)(n0blk + n) * H + (kg - H)))
                : (Wa + (size_t)(n0blk + n) * KTOT + kg);
            bR[r] = *reinterpret_cast<const float4*>(src);
        }
    };

    auto store_split = [&]() {
        #pragma unroll
        for (int r = 0; r < 2; r++) {
            int m = lm + r * 32;
            float v[4] = {aR[r].x, aR[r].y, aR[r].z, aR[r].w};
            #pragma unroll
            for (int j = 0; j < 4; j++) {
                float hi, lo; split_tf32(v[j], hi, lo);
                AsH[m][lk4 + j] = hi;
                AsL[m][lk4 + j] = lo;
            }
        }
        #pragma unroll
        for (int r = 0; r < BR; r++) {
            int n = lm + r * 32;
            float v[4] = {bR[r].x, bR[r].y, bR[r].z, bR[r].w};
            #pragma unroll
            for (int j = 0; j < 4; j++) {
                float hi, lo; split_tf32(v[j], hi, lo);
                BsH[n][lk4 + j] = hi;
                BsL[n][lk4 + j] = lo;
            }
        }
    };

    float c[NF][4];
    #pragma unroll
    for (int nf = 0; nf < NF; nf++)
        #pragma unroll
        for (int j = 0; j < 4; j++) c[nf][j] = 0.f;

    gload(0);
    for (int k0 = 0; k0 < KTOT; k0 += BK) {
        store_split();
        __syncthreads();
        if (k0 + BK < KTOT) gload(k0 + BK);    // prefetch next tile into regs

        #pragma unroll
        for (int ks = 0; ks < BK / 8; ks++) {
            const int kk = ks * 8;
            const int ra = m0 + gid, rb = m0 + gid + 8;
            uint32_t ah0 = __float_as_uint(AsH[ra][kk + tig]);
            uint32_t ah1 = __float_as_uint(AsH[rb][kk + tig]);
            uint32_t ah2 = __float_as_uint(AsH[ra][kk + tig + 4]);
            uint32_t ah3 = __float_as_uint(AsH[rb][kk + tig + 4]);
            uint32_t al0 = __float_as_uint(AsL[ra][kk + tig]);
            uint32_t al1 = __float_as_uint(AsL[rb][kk + tig]);
            uint32_t al2 = __float_as_uint(AsL[ra][kk + tig + 4]);
            uint32_t al3 = __float_as_uint(AsL[rb][kk + tig + 4]);

            #pragma unroll
            for (int nf = 0; nf < NF; nf++) {
                int n = n0w + nf * 8 + gid;
                uint32_t bh0 = __float_as_uint(BsH[n][kk + tig]);
                uint32_t bh1 = __float_as_uint(BsH[n][kk + tig + 4]);
                uint32_t bl0 = __float_as_uint(BsL[n][kk + tig]);
                uint32_t bl1 = __float_as_uint(BsL[n][kk + tig + 4]);
                // C += Al*Bh + Ah*Bl + Ah*Bh  (3xTF32 ~ fp32)
                mma_tf32(c[nf], al0, al1, al2, al3, bh0, bh1);
                mma_tf32(c[nf], ah0, ah1, ah2, ah3, bl0, bl1);
                mma_tf32(c[nf], ah0, ah1, ah2, ah3, bh0, bh1);
            }
        }
        __syncthreads();
    }

    // ---- epilogue: bias + store (float2 per row-fragment) ----
    const int mr0 = m0 + gid;
    const int mr1 = m0 + gid + 8;
    #pragma unroll
    for (int nf = 0; nf < NF; nf++) {
        int nn = n0blk + n0w + nf * 8 + tig * 2;
        float b0 = bias1[nn]     + (CONCAT ? bias2[nn]     : 0.f);
        float b1 = bias1[nn + 1] + (CONCAT ? bias2[nn + 1] : 0.f);
        float2 v0 = make_float2(c[nf][0] + b0, c[nf][1] + b1);
        float2 v1 = make_float2(c[nf][2] + b0, c[nf][3] + b1);
        *reinterpret_cast<float2*>(out + (size_t)mr0 * ldc + nn) = v0;
        *reinterpret_cast<float2*>(out + (size_t)mr1 * ldc + nn) = v1;
    }
}

// ---------------------------------------------------------------------------
// LSTM cell elementwise (PyTorch gate order i,f,g,o)
// ---------------------------------------------------------------------------
__global__ void cell_kernel() {
    int i = blockIdx.x * blockDim.x + threadIdx.x;   // B*H
    int b = i >> 10;
    int j = i & (H - 1);
    const float* g = g_gates + b * GATES;
    float ig = g[j], fg = g[j + H], gg = g[j + 2 * H], og = g[j + 3 * H];
    float c  = g_c[i];
    float si = 1.f / (1.f + expf(-ig));
    float sf = 1.f / (1.f + expf(-fg));
    float so = 1.f / (1.f + expf(-og));
    float cn = sf * c + si * tanhf(gg);
    float hn = so * tanhf(cn);
    g_c[i] = cn;
    g_h[i] = hn;
}

// ---------------------------------------------------------------------------
// Per-batch-row: argmax (first-index tiebreak), softmax EOS prob,
// greedy feedback gather x_next = E[argmax]
// ---------------------------------------------------------------------------
__global__ __launch_bounds__(256)
void softmax_argmax(const float* __restrict__ logits, const float* __restrict__ E,
                    float* __restrict__ mask_out) {
    const int b   = blockIdx.x;
    const int tid = threadIdx.x;
    const float* row = logits + (size_t)b * V;

    float best = -INFINITY; int besti = 0x7fffffff;
    for (int v = tid; v < V; v += 256) {
        float x = row[v];
        if (x > best) { best = x; besti = v; }   // scan order keeps lowest index
    }
    __shared__ float smax[256];
    __shared__ int   sidx[256];
    smax[tid] = best; sidx[tid] = besti;
    __syncthreads();
    for (int s = 128; s > 0; s >>= 1) {
        if (tid < s) {
            float o = smax[tid + s]; int oi = sidx[tid + s];
            if (o > smax[tid] || (o == smax[tid] && oi < sidx[tid])) {
                smax[tid] = o; sidx[tid] = oi;
            }
        }
        __syncthreads();
    }
    const float gmax = smax[0];
    const int   amax = sidx[0];

    float sum = 0.f;
    for (int v = tid; v < V; v += 256) sum += expf(row[v] - gmax);
    __shared__ float ssum[256];
    ssum[tid] = sum;
    __syncthreads();
    for (int s = 128; s > 0; s >>= 1) {
        if (tid < s) ssum[tid] += ssum[tid + s];
        __syncthreads();
    }
    if (tid == 0) mask_out[b] = expf(row[EOS_INDEX] - gmax) / ssum[0];

    // greedy feedback: x_next = E[argmax]
    for (int k = tid; k < H; k += 256)
        g_x[b * H + k] = E[(size_t)amax * H + k];
}

// ---------------------------------------------------------------------------
extern "C" void kernel_launch(void* const* d_in, const int* in_sizes, int n_in,
                              void* d_out, int out_size) {
    const float* E    = (const float*)d_in[0];
    const float* Wih  = (const float*)d_in[1];
    const float* Whh  = (const float*)d_in[2];
    const float* bih  = (const float*)d_in[3];
    const float* bhh  = (const float*)d_in[4];
    const float* Wout = (const float*)d_in[5];
    const float* bout = (const float*)d_in[6];
    const float* eh   = (const float*)d_in[7];
    const float* ec   = (const float*)d_in[8];

    float* out   = (float*)d_out;                       // [T][B][V] logits
    float* masks = out + (size_t)T * B * V;             // [T][B]

    // Resolve DEVICE address of g_gates (host shadow addr would silently
    // write host memory via ATS on GB300).
    void* gates_dev = nullptr;
    cudaGetSymbolAddress(&gates_dev, g_gates);
    float* gates_ptr = (float*)gates_dev;

    init_kernel<<<(B * H) / 256, 256>>>(E, eh, ec);
    for (int t = 0; t < T; t++) {
        float* lg = out + (size_t)t * B * V;
        // gates: [64 x 4096] = [x|h] * [Wih|Whh]^T, BN=32 -> 128 blocks
        mma_gemm<2 * H, 32, true><<<GATES / 32, 256>>>(
            Wih, Whh, bih, bhh, gates_ptr, GATES);
        cell_kernel<<<(B * H) / 256, 256>>>();
        // logits: [64 x 32000] = h * Wout^T, BN=64 -> 500 blocks
        mma_gemm<H, 64, false><<<V / 64, 256>>>(
            Wout, nullptr, bout, nullptr, lg, V);
        softmax_argmax<<<B, 256>>>(lg, E, masks + t * B);
    }
}